// round 10
// baseline (speedup 1.0000x reference)
#include <cuda_runtime.h>
#include <cstdint>

#define NB 256
#define IN_F 1024
#define B_EXTRA 256
#define KDIM 16
#define OUT_F 1280
#define JDIM 4096            // B_EXTRA * KDIM

// ---------------- device scratch ----------------
__device__ float g_M[NB * JDIM];   // 4 MB

// ---------------- helpers ----------------
__device__ __forceinline__ uint32_t smem_u32(const void* p) {
    uint32_t a;
    asm("{ .reg .u64 t; cvta.to.shared.u64 t, %1; cvt.u32.u64 %0, t; }" : "=r"(a) : "l"(p));
    return a;
}
__device__ __forceinline__ void cp16(uint32_t dst, const void* src) {
    asm volatile("cp.async.cg.shared.global [%0], [%1], 16;" :: "r"(dst), "l"(src) : "memory");
}
#define CP_COMMIT() asm volatile("cp.async.commit_group;" ::: "memory")
#define CP_WAITG1() asm volatile("cp.async.wait_group 1;" ::: "memory")
#define CP_WAITG0() asm volatile("cp.async.wait_group 0;" ::: "memory")

__device__ __forceinline__ uint32_t lds32(uint32_t a) {
    uint32_t v;
    asm volatile("ld.shared.b32 %0, [%1];" : "=r"(v) : "r"(a));
    return v;
}
// m16n8k8 tf32 mma (fp32 bits passed raw = tf32 truncation)
__device__ __forceinline__ void mma_tf32(float* d, const uint32_t* a, const uint32_t* b) {
    asm volatile("mma.sync.aligned.m16n8k8.row.col.f32.tf32.tf32.f32 "
        "{%0,%1,%2,%3}, {%4,%5,%6,%7}, {%8,%9}, {%0,%1,%2,%3};"
        : "+f"(d[0]), "+f"(d[1]), "+f"(d[2]), "+f"(d[3])
        : "r"(a[0]), "r"(a[1]), "r"(a[2]), "r"(a[3]), "r"(b[0]), "r"(b[1]));
}
__device__ __forceinline__ int vad4add(uint32_t a, uint32_t b, int c) {
    int d;
    asm("vabsdiff4.u32.s32.s32.add %0, %1, %2, %3;" : "=r"(d) : "r"(a), "r"(b), "r"(c));
    return d;
}
__device__ __forceinline__ float ex2f(float v) {
    float y;
    asm("ex2.approx.f32 %0, %1;" : "=f"(y) : "f"(v));
    return y;
}

// ---------------------------------------------------------------------------
// Kernel 1: TF32 GEMM  M(256x4096) = x(256x1024) @ W(1024x4096), fp32 in/out.
// CTA 128(m) x 64(n), BK=32, 32 k-tiles, 3-stage cp.async pipeline,
// 8 warps (warp tile 32x32). Grid (64, 2) = 128 CTAs.
// A smem rows padded to 36 floats, B rows to 72 floats (conflict-free LDS).
// ---------------------------------------------------------------------------
#define BM 128
#define BN 64
#define BK 32
#define NT_K 32
#define A_ROW 36                       // floats (144 B)
#define B_ROW 72                       // floats (288 B)
#define A_BYTES (BM * A_ROW * 4)       // 18432
#define B_BYTES (BK * B_ROW * 4)       // 9216
#define STG (A_BYTES + B_BYTES)        // 27648
#define SA_OFF(s) ((s) * STG)
#define SB_OFF(s) ((s) * STG + A_BYTES)
#define GEMM_SMEM (3 * STG)            // 82944

__global__ __launch_bounds__(256) void gemm_kernel(const float* __restrict__ x,
                                                   const float* __restrict__ W) {
    extern __shared__ __align__(16) char smem[];
    const uint32_t sbase = smem_u32(smem);
    const int tid = threadIdx.x;
    const int wid = tid >> 5;
    const int lane = tid & 31;
    const int m0 = blockIdx.y * BM;
    const int n0 = blockIdx.x * BN;
    const int wm = (wid >> 1) * 32;
    const int wn = (wid & 1) * 32;

    auto issue_tile = [&](int t) {
        const int s = t % 3;
        const int kk = t * BK;
        const uint32_t SA = sbase + SA_OFF(s);
        const uint32_t SB = sbase + SB_OFF(s);
#pragma unroll
        for (int q = 0; q < 4; q++) {          // A: 1024 chunks (128r x 8c)
            const int i = tid + q * 256;
            const int r = i >> 3, c = i & 7;
            cp16(SA + (r * A_ROW + c * 4) * 4, x + (size_t)(m0 + r) * IN_F + kk + c * 4);
        }
#pragma unroll
        for (int q = 0; q < 2; q++) {          // B: 512 chunks (32r x 16c)
            const int i = tid + q * 256;
            const int r = i >> 4, c = i & 15;
            cp16(SB + (r * B_ROW + c * 4) * 4, W + (size_t)(kk + r) * JDIM + n0 + c * 4);
        }
        CP_COMMIT();
    };

    float acc[2][4][4] = {};

    issue_tile(0);
    issue_tile(1);

    const int qr = lane >> 2;   // 0..7
    const int qc = lane & 3;    // 0..3

    for (int t = 0; t < NT_K; t++) {
        if (t + 2 < NT_K) CP_WAITG1(); else CP_WAITG0();
        __syncthreads();
        if (t + 2 < NT_K) issue_tile(t + 2);

        const int s = t % 3;
        const uint32_t SA = sbase + SA_OFF(s);
        const uint32_t SB = sbase + SB_OFF(s);
#pragma unroll
        for (int k8 = 0; k8 < BK; k8 += 8) {
            uint32_t af[2][4], bf[4][2];
#pragma unroll
            for (int mt = 0; mt < 2; mt++) {
                const uint32_t base = SA + (((wm + mt * 16 + qr) * A_ROW) + k8 + qc) * 4;
                af[mt][0] = lds32(base);
                af[mt][1] = lds32(base + 8 * A_ROW * 4);
                af[mt][2] = lds32(base + 4 * 4);
                af[mt][3] = lds32(base + (8 * A_ROW + 4) * 4);
            }
#pragma unroll
            for (int nt = 0; nt < 4; nt++) {
                const uint32_t base = SB + (((k8 + qc) * B_ROW) + wn + nt * 8 + qr) * 4;
                bf[nt][0] = lds32(base);
                bf[nt][1] = lds32(base + 4 * B_ROW * 4);
            }
#pragma unroll
            for (int mt = 0; mt < 2; mt++)
#pragma unroll
                for (int j = 0; j < 4; j++)
                    mma_tf32(acc[mt][j], af[mt], bf[j]);
        }
        __syncthreads();
    }

    // epilogue: write fp32 tiles to g_M (c frag: rows qr/qr+8, cols qc*2+{0,1})
#pragma unroll
    for (int mt = 0; mt < 2; mt++)
#pragma unroll
        for (int j = 0; j < 4; j++) {
            const size_t base = (size_t)(m0 + wm + mt * 16 + qr) * JDIM +
                                n0 + wn + j * 8 + qc * 2;
            *(float2*)(g_M + base)            = make_float2(acc[mt][j][0], acc[mt][j][1]);
            *(float2*)(g_M + base + 8 * JDIM) = make_float2(acc[mt][j][2], acc[mt][j][3]);
        }
}

// ---------------------------------------------------------------------------
// Kernel 2: pairwise L1 + exp-sum via int8 SAD.
// Grid = 128 blocks x 512 threads; thread = (m = tid&255, grp = tid>>8);
// block handles b = 2*blk + grp. Both groups prep their own sQ concurrently.
// Folded x-copy (one float4 per thread). Full 256-n loop per thread.
// ---------------------------------------------------------------------------
__global__ __launch_bounds__(512) void pairwise_kernel(const float* __restrict__ x,
                                                       float* __restrict__ out) {
    __shared__ __align__(16) uint4 sQ[2][NB];   // 8 KB quantized rows
    __shared__ float sWmax[16];
    const int blk = blockIdx.x;
    const int tid = threadIdx.x;
    const int m = tid & 255;
    const int grp = tid >> 8;
    const int b = blk * 2 + grp;
    const int lane = tid & 31;

    // folded x-copy: 128 blocks x 512 thr x 1 float4 = 65536 float4s = all of x
    {
        const int gidx = blk * 512 + tid;
        const int row = gidx >> 8;
        const int c = gidx & 255;
        ((float4*)(out + (size_t)row * OUT_F))[c] =
            ((const float4*)(x + (size_t)row * IN_F))[c];
    }

    // load own M row (16 fp32) for this group's b
    const float* rowp = g_M + (size_t)m * JDIM + b * KDIM;
    float f[16];
#pragma unroll
    for (int q = 0; q < 4; q++) {
        float4 v = ((const float4*)rowp)[q];
        f[4 * q] = v.x; f[4 * q + 1] = v.y; f[4 * q + 2] = v.z; f[4 * q + 3] = v.w;
    }

    // per-group max|.| (warps don't straddle groups: 8 warps per group)
    float mx = fabsf(f[0]);
#pragma unroll
    for (int k = 1; k < 16; k++) mx = fmaxf(mx, fabsf(f[k]));
#pragma unroll
    for (int o = 16; o; o >>= 1) mx = fmaxf(mx, __shfl_xor_sync(0xFFFFFFFFu, mx, o));
    if (lane == 0) sWmax[tid >> 5] = mx;
    __syncthreads();
    float bm = sWmax[grp * 8];
#pragma unroll
    for (int w = 1; w < 8; w++) bm = fmaxf(bm, sWmax[grp * 8 + w]);
    bm = fmaxf(bm, 1e-20f);

    // quantize own row, publish to group's sQ
    const float s = 127.0f / bm;
    uint32_t q32[4];
#pragma unroll
    for (int q = 0; q < 4; q++) {
        const int q0 = __float2int_rn(f[4 * q] * s);
        const int q1 = __float2int_rn(f[4 * q + 1] * s);
        const int q2 = __float2int_rn(f[4 * q + 2] * s);
        const int q3 = __float2int_rn(f[4 * q + 3] * s);
        q32[q] = (q0 & 255) | ((q1 & 255) << 8) | ((q2 & 255) << 16) | (q3 << 24);
    }
    sQ[grp][m] = make_uint4(q32[0], q32[1], q32[2], q32[3]);
    __syncthreads();

    const float negc = -bm * (1.44269504088896f / 127.0f);
    const uint4* Q = sQ[grp];
    float acc0 = 0.0f, acc1 = 0.0f;

#pragma unroll 4
    for (int i = 0; i < NB / 2; i++) {
        const uint4 qa = Q[2 * i];
        const uint4 qb = Q[2 * i + 1];
        int sa = vad4add(qa.x, q32[0], 0);
        int sb = vad4add(qb.x, q32[0], 0);
        int sa2 = vad4add(qa.y, q32[1], 0);
        int sb2 = vad4add(qb.y, q32[1], 0);
        sa = vad4add(qa.z, q32[2], sa);
        sb = vad4add(qb.z, q32[2], sb);
        sa2 = vad4add(qa.w, q32[3], sa2);
        sb2 = vad4add(qb.w, q32[3], sb2);
        acc0 += ex2f((float)(sa + sa2) * negc);
        acc1 += ex2f((float)(sb + sb2) * negc);
    }

    // self term exp(0)=1 subtracted per reference.
    out[(size_t)m * OUT_F + IN_F + b] = (acc0 + acc1) - 1.0f;
}

extern "C" void kernel_launch(void* const* d_in, const int* in_sizes, int n_in,
                              void* d_out, int out_size) {
    const float* x = (const float*)d_in[0];   // (256, 1024)
    const float* T = (const float*)d_in[1];   // (1024, 256, 16) == W[k][n]
    float* out = (float*)d_out;               // (256, 1280)

    cudaFuncSetAttribute(gemm_kernel, cudaFuncAttributeMaxDynamicSharedMemorySize, GEMM_SMEM);
    gemm_kernel<<<dim3(JDIM / BN, NB / BM), 256, GEMM_SMEM>>>(x, T);

    pairwise_kernel<<<B_EXTRA / 2, 512>>>(x, out);
}

// round 11
// speedup vs baseline: 1.3268x; 1.3268x over previous
#include <cuda_runtime.h>
#include <cuda_bf16.h>
#include <cstdint>

#define NB 256
#define IN_F 1024
#define B_EXTRA 256
#define KDIM 16
#define OUT_F 1280
#define JDIM 4096            // B_EXTRA * KDIM

// ---------------- device scratch ----------------
__device__ float g_M[NB * JDIM];                       // 4 MB
__device__ __nv_bfloat16 g_xb[NB * IN_F];              // 512 KB [m][k]
__device__ __nv_bfloat16 g_Wb[(size_t)IN_F * JDIM];    // 8 MB  [k][n]

// ---------------- helpers ----------------
__device__ __forceinline__ uint32_t smem_u32(const void* p) {
    uint32_t a;
    asm("{ .reg .u64 t; cvta.to.shared.u64 t, %1; cvt.u32.u64 %0, t; }" : "=r"(a) : "l"(p));
    return a;
}
#define SWZ(x) ((x) ^ (((x) >> 3) & 0x70))

__device__ __forceinline__ void cp16(uint32_t dst, const void* src) {
    asm volatile("cp.async.cg.shared.global [%0], [%1], 16;" :: "r"(dst), "l"(src) : "memory");
}
#define CP_COMMIT() asm volatile("cp.async.commit_group;" ::: "memory")
#define CP_WAITG1() asm volatile("cp.async.wait_group 1;" ::: "memory")
#define CP_WAITG0() asm volatile("cp.async.wait_group 0;" ::: "memory")

__device__ __forceinline__ void ldsm_x4(uint32_t* r, uint32_t a) {
    asm volatile("ldmatrix.sync.aligned.m8n8.x4.shared.b16 {%0,%1,%2,%3}, [%4];"
        : "=r"(r[0]), "=r"(r[1]), "=r"(r[2]), "=r"(r[3]) : "r"(a));
}
__device__ __forceinline__ void ldsm_x4_t(uint32_t* r, uint32_t a) {
    asm volatile("ldmatrix.sync.aligned.m8n8.x4.trans.shared.b16 {%0,%1,%2,%3}, [%4];"
        : "=r"(r[0]), "=r"(r[1]), "=r"(r[2]), "=r"(r[3]) : "r"(a));
}
__device__ __forceinline__ void mma_16816(float* d, const uint32_t* a, const uint32_t* b) {
    asm volatile("mma.sync.aligned.m16n8k16.row.col.f32.bf16.bf16.f32 "
        "{%0,%1,%2,%3}, {%4,%5,%6,%7}, {%8,%9}, {%0,%1,%2,%3};"
        : "+f"(d[0]), "+f"(d[1]), "+f"(d[2]), "+f"(d[3])
        : "r"(a[0]), "r"(a[1]), "r"(a[2]), "r"(a[3]), "r"(b[0]), "r"(b[1]));
}
__device__ __forceinline__ uint32_t cvt_bf16x2(float flo, float fhi) {
    uint32_t d;
    asm("cvt.rn.bf16x2.f32 %0, %1, %2;" : "=r"(d) : "f"(fhi), "f"(flo));
    return d;
}
__device__ __forceinline__ int vad4add(uint32_t a, uint32_t b, int c) {
    int d;
    asm("vabsdiff4.u32.s32.s32.add %0, %1, %2, %3;" : "=r"(d) : "r"(a), "r"(b), "r"(c));
    return d;
}
__device__ __forceinline__ float ex2f(float v) {
    float y;
    asm("ex2.approx.f32 %0, %1;" : "=f"(y) : "f"(v));
    return y;
}

// ---------------------------------------------------------------------------
// Kernel 1: prep — fp32 -> bf16, 16 elems (4 independent LDG.128) per thread.
// Blocks 0..1023: W (4M elems). Blocks 1024..1087: x (256K elems).
// ---------------------------------------------------------------------------
__global__ __launch_bounds__(256) void prep_kernel(const float* __restrict__ x,
                                                   const float* __restrict__ W) {
    const int blk = blockIdx.x;
    const int tid = threadIdx.x;
    const float* src;
    __nv_bfloat16* dst;
    size_t i;
    if (blk < 1024) {
        i = ((size_t)blk * 256 + tid) * 16;
        src = W; dst = g_Wb;
    } else {
        i = ((size_t)(blk - 1024) * 256 + tid) * 16;
        src = x; dst = g_xb;
    }
    float4 v[4];
#pragma unroll
    for (int q = 0; q < 4; q++) v[q] = *(const float4*)(src + i + q * 4);
#pragma unroll
    for (int q = 0; q < 4; q += 2) {
        uint4 o;
        o.x = cvt_bf16x2(v[q].x, v[q].y);     o.y = cvt_bf16x2(v[q].z, v[q].w);
        o.z = cvt_bf16x2(v[q + 1].x, v[q + 1].y); o.w = cvt_bf16x2(v[q + 1].z, v[q + 1].w);
        *(uint4*)(dst + i + q * 4) = o;
    }
}

// ---------------------------------------------------------------------------
// Kernel 2: bf16 HMMA GEMM, 3-stage cp.async pipeline (R8 proven config).
// CTA 128x64, BK=64, 8 warps. Grid (64, 2) = 128 CTAs.
// ---------------------------------------------------------------------------
#define BM 128
#define BN 64
#define BK 64
#define NT_K 16
#define STG_SZ 24576
#define SA(s) ((s) * STG_SZ)
#define SB(s) ((s) * STG_SZ + 16384)
#define GEMM_SMEM (3 * STG_SZ)

__global__ __launch_bounds__(256) void gemm_kernel() {
    extern __shared__ __align__(1024) char smem[];
    const uint32_t sbase = smem_u32(smem);
    const int tid = threadIdx.x;
    const int wid = tid >> 5;
    const int lane = tid & 31;
    const int m0 = blockIdx.y * BM;
    const int n0 = blockIdx.x * BN;
    const int wm = (wid >> 1) * 32;
    const int wn = (wid & 1) * 32;
    const int c8 = tid & 7;

    auto issue_tile = [&](int t) {
        const int s = t % 3;
        const int kk = t * BK;
        const uint32_t Ab = sbase + SA(s);
        const uint32_t Bb = sbase + SB(s);
#pragma unroll
        for (int q = 0; q < 4; q++) {
            const int r = (tid + q * 256) >> 3;
            cp16(Ab + SWZ(r * 128 + c8 * 16),
                 g_xb + (size_t)(m0 + r) * IN_F + kk + c8 * 8);
        }
#pragma unroll
        for (int q = 0; q < 2; q++) {
            const int r = (tid + q * 256) >> 3;
            cp16(Bb + SWZ(r * 128 + c8 * 16),
                 g_Wb + (size_t)(kk + r) * JDIM + n0 + c8 * 8);
        }
        CP_COMMIT();
    };

    float acc[2][4][4] = {};

    issue_tile(0);
    issue_tile(1);

    for (int t = 0; t < NT_K; t++) {
        if (t + 2 < NT_K) CP_WAITG1(); else CP_WAITG0();
        __syncthreads();
        if (t + 2 < NT_K) issue_tile(t + 2);

        const int s = t % 3;
        const uint32_t Ab = sbase + SA(s);
        const uint32_t Bb = sbase + SB(s);
#pragma unroll
        for (int st = 0; st < 4; st++) {
            uint32_t af[2][4], bf[2][4];
#pragma unroll
            for (int mt = 0; mt < 2; mt++)
                ldsm_x4(af[mt], Ab + SWZ((wm + mt * 16 + (lane & 15)) * 128 +
                                         st * 32 + (lane >> 4) * 16));
#pragma unroll
            for (int nt = 0; nt < 2; nt++)
                ldsm_x4_t(bf[nt], Bb + SWZ((st * 16 + (lane & 15)) * 128 +
                                           (wn + nt * 16) * 2 + (lane >> 4) * 16));
#pragma unroll
            for (int mt = 0; mt < 2; mt++)
#pragma unroll
                for (int j = 0; j < 4; j++)
                    mma_16816(acc[mt][j], af[mt], bf[j >> 1] + (j & 1) * 2);
        }
        __syncthreads();
    }

    const int g = lane >> 2, tig = lane & 3;
#pragma unroll
    for (int mt = 0; mt < 2; mt++)
#pragma unroll
        for (int j = 0; j < 4; j++) {
            const size_t base = (size_t)(m0 + wm + mt * 16 + g) * JDIM +
                                n0 + wn + j * 8 + tig * 2;
            *(float2*)(g_M + base)            = make_float2(acc[mt][j][0], acc[mt][j][1]);
            *(float2*)(g_M + base + 8 * JDIM) = make_float2(acc[mt][j][2], acc[mt][j][3]);
        }
}

// ---------------------------------------------------------------------------
// Kernel 3: pairwise L1 + exp-sum, int8 SAD, 4-way n-split.
// Grid = 256 blocks (one per b) x 1024 threads: m = tid&255, q4 = tid>>8.
// Each thread sums n in [q4*64, q4*64+64); partials reduced via smem.
// Magic-number int->float + single FFMA feeds ex2 (no I2F/FMUL).
// x-copy done by the q4==3 group during the prologue.
// ---------------------------------------------------------------------------
__global__ __launch_bounds__(1024, 2) void pairwise_kernel(const float* __restrict__ x,
                                                           float* __restrict__ out) {
    __shared__ __align__(16) uint4 sQ[NB];    // 4 KB quantized rows
    __shared__ float sWmax[8];
    __shared__ float sP[NB][4];               // 4 KB partials
    const int b = blockIdx.x;
    const int tid = threadIdx.x;
    const int m = tid & 255;
    const int q4 = tid >> 8;
    const int lane = tid & 31;

    if (q4 == 0) {
        // load own M row, warp max
        const float* rowp = g_M + (size_t)m * JDIM + b * KDIM;
        float f[16];
#pragma unroll
        for (int q = 0; q < 4; q++) {
            float4 v = ((const float4*)rowp)[q];
            f[4 * q] = v.x; f[4 * q + 1] = v.y; f[4 * q + 2] = v.z; f[4 * q + 3] = v.w;
        }
        float mx = fabsf(f[0]);
#pragma unroll
        for (int k = 1; k < 16; k++) mx = fmaxf(mx, fabsf(f[k]));
#pragma unroll
        for (int o = 16; o; o >>= 1) mx = fmaxf(mx, __shfl_xor_sync(0xFFFFFFFFu, mx, o));
        if (lane == 0) sWmax[tid >> 5] = mx;
        __syncthreads();   // barrier 1
        float bm = sWmax[0];
#pragma unroll
        for (int w = 1; w < 8; w++) bm = fmaxf(bm, sWmax[w]);
        bm = fmaxf(bm, 1e-20f);
        const float s = 127.0f / bm;
        uint32_t q32[4];
#pragma unroll
        for (int q = 0; q < 4; q++) {
            const int a0 = __float2int_rn(f[4 * q] * s);
            const int a1 = __float2int_rn(f[4 * q + 1] * s);
            const int a2 = __float2int_rn(f[4 * q + 2] * s);
            const int a3 = __float2int_rn(f[4 * q + 3] * s);
            q32[q] = (a0 & 255) | ((a1 & 255) << 8) | ((a2 & 255) << 16) | (a3 << 24);
        }
        sQ[m] = make_uint4(q32[0], q32[1], q32[2], q32[3]);
    } else {
        if (q4 == 3) {
            // folded x-copy: 256 threads x 256 blocks x 1 float4 = all of x
            const int gidx = b * 256 + m;
            const int row = gidx >> 8;
            const int c = gidx & 255;
            ((float4*)(out + (size_t)row * OUT_F))[c] =
                ((const float4*)(x + (size_t)row * IN_F))[c];
        }
        __syncthreads();   // barrier 1
    }
    __syncthreads();       // barrier 2: sQ published

    float bm = sWmax[0];
#pragma unroll
    for (int w = 1; w < 8; w++) bm = fmaxf(bm, sWmax[w]);
    bm = fmaxf(bm, 1e-20f);
    const float negc = -bm * (1.44269504088896f / 127.0f);
    const float offs = -8388608.0f * negc;   // cancels the magic bias

    const uint4 mq = sQ[m];
    const uint32_t myq0 = mq.x, myq1 = mq.y, myq2 = mq.z, myq3 = mq.w;

    float acc0 = 0.0f, acc1 = 0.0f;
    const uint4* Q = sQ + q4 * 64;
#pragma unroll 8
    for (int i = 0; i < 32; i++) {
        const uint4 qa = Q[2 * i];
        const uint4 qb = Q[2 * i + 1];
        int sa = vad4add(qa.x, myq0, 0);
        int sb = vad4add(qb.x, myq0, 0);
        sa = vad4add(qa.y, myq1, sa);
        sb = vad4add(qb.y, myq1, sb);
        sa = vad4add(qa.z, myq2, sa);
        sb = vad4add(qb.z, myq2, sb);
        sa = vad4add(qa.w, myq3, sa);
        sb = vad4add(qb.w, myq3, sb);
        // float(sa) via magic-number: asfloat(0x4B000000|sa) = 8388608 + sa (exact)
        const float fa = __uint_as_float(0x4B000000u | (uint32_t)sa);
        const float fb = __uint_as_float(0x4B000000u | (uint32_t)sb);
        acc0 += ex2f(fmaf(fa, negc, offs));
        acc1 += ex2f(fmaf(fb, negc, offs));
    }
    sP[m][q4] = acc0 + acc1;
    __syncthreads();       // barrier 3

    if (q4 == 0)
        out[(size_t)m * OUT_F + IN_F + b] =
            ((sP[m][0] + sP[m][1]) + (sP[m][2] + sP[m][3])) - 1.0f;
}

extern "C" void kernel_launch(void* const* d_in, const int* in_sizes, int n_in,
                              void* d_out, int out_size) {
    const float* x = (const float*)d_in[0];   // (256, 1024)
    const float* T = (const float*)d_in[1];   // (1024, 256, 16) == W[k][n]
    float* out = (float*)d_out;               // (256, 1280)

    prep_kernel<<<1088, 256>>>(x, T);

    cudaFuncSetAttribute(gemm_kernel, cudaFuncAttributeMaxDynamicSharedMemorySize, GEMM_SMEM);
    gemm_kernel<<<dim3(JDIM / BN, NB / BM), 256, GEMM_SMEM>>>();

    pairwise_kernel<<<B_EXTRA, 1024>>>(x, out);
}